// round 2
// baseline (speedup 1.0000x reference)
#include <cuda_runtime.h>
#include <cstdint>

// Shapes (fixed by the problem): B=32, C=4, S=256, L=Din=Dout=256
#define SB 32
#define SC 4
#define SS 256

// Scratch (static device globals — allowed; no runtime allocation)
__device__ float g_corr[SB * SS * SS];        //  8M floats
__device__ float g_adj [SB * SS * SS];        //  8M floats
__device__ float g_x   [SB * SC * SS * SS];   // 32M floats

// ---------------------------------------------------------------------------
// Generic tiled SGEMM: C = A @ B (+bias), or C = A @ B^T when TRANSB.
// A: [M,K] row-major (lda=K). B: [K,N] (ldb=N) or [N,K] (ldb=K) when TRANSB.
// Block tile 128x128, K-step 16, 256 threads, 8x8 microtile per thread.
// Batched via blockIdx.z; A batch index = bz / adiv (adjacency reuse across C).
// ---------------------------------------------------------------------------
template<bool TRANSB, bool BIAS>
__global__ __launch_bounds__(256)
void gemm_kernel(const float* __restrict__ A, const float* __restrict__ B,
                 const float* __restrict__ bias, float* __restrict__ C,
                 int M, int N, int K, int adiv,
                 long strideA, long strideB, long strideC)
{
    const int bz = blockIdx.z;
    A += (long)(bz / adiv) * strideA;
    B += (long)bz * strideB;
    C += (long)bz * strideC;

    __shared__ __align__(16) float As[16][132];
    __shared__ __align__(16) float Bs[16][132];

    const int tid = threadIdx.x;
    const int tx = tid & 15;        // column group (0..15)
    const int ty = tid >> 4;        // row group (0..15)
    const int row0 = blockIdx.y * 128;
    const int col0 = blockIdx.x * 128;

    const int lm  = tid >> 2;       // 0..63 (row within tile for xpose loads)
    const int lk4 = (tid & 3) * 4;  // 0,4,8,12 (k offset)

    float acc[8][8];
    #pragma unroll
    for (int i = 0; i < 8; i++)
        #pragma unroll
        for (int j = 0; j < 8; j++) acc[i][j] = 0.0f;

    for (int k0 = 0; k0 < K; k0 += 16) {
        // ---- load A tile (transpose into As[k][m]) ----
        {
            float4 v0 = *(const float4*)(A + (long)(row0 + lm     ) * K + k0 + lk4);
            float4 v1 = *(const float4*)(A + (long)(row0 + lm + 64) * K + k0 + lk4);
            As[lk4 + 0][lm] = v0.x; As[lk4 + 1][lm] = v0.y;
            As[lk4 + 2][lm] = v0.z; As[lk4 + 3][lm] = v0.w;
            As[lk4 + 0][lm + 64] = v1.x; As[lk4 + 1][lm + 64] = v1.y;
            As[lk4 + 2][lm + 64] = v1.z; As[lk4 + 3][lm + 64] = v1.w;
        }
        // ---- load B tile ----
        if (TRANSB) {
            // B is [N,K]; Bs[k][n] = B[n][k] (transpose on load)
            float4 v0 = *(const float4*)(B + (long)(col0 + lm     ) * K + k0 + lk4);
            float4 v1 = *(const float4*)(B + (long)(col0 + lm + 64) * K + k0 + lk4);
            Bs[lk4 + 0][lm] = v0.x; Bs[lk4 + 1][lm] = v0.y;
            Bs[lk4 + 2][lm] = v0.z; Bs[lk4 + 3][lm] = v0.w;
            Bs[lk4 + 0][lm + 64] = v1.x; Bs[lk4 + 1][lm + 64] = v1.y;
            Bs[lk4 + 2][lm + 64] = v1.z; Bs[lk4 + 3][lm + 64] = v1.w;
        } else {
            // B is [K,N]; straight copy
            const int bk  = tid >> 5;         // 0..7
            const int bn4 = (tid & 31) * 4;   // 0..124
            float4 v0 = *(const float4*)(B + (long)(k0 + bk    ) * N + col0 + bn4);
            float4 v1 = *(const float4*)(B + (long)(k0 + bk + 8) * N + col0 + bn4);
            *(float4*)(&Bs[bk    ][bn4]) = v0;
            *(float4*)(&Bs[bk + 8][bn4]) = v1;
        }
        __syncthreads();

        #pragma unroll
        for (int kk = 0; kk < 16; kk++) {
            float a[8], b[8];
            *(float4*)&a[0] = *(const float4*)&As[kk][ty * 8];
            *(float4*)&a[4] = *(const float4*)&As[kk][ty * 8 + 4];
            *(float4*)&b[0] = *(const float4*)&Bs[kk][tx * 8];
            *(float4*)&b[4] = *(const float4*)&Bs[kk][tx * 8 + 4];
            #pragma unroll
            for (int i = 0; i < 8; i++)
                #pragma unroll
                for (int j = 0; j < 8; j++)
                    acc[i][j] = fmaf(a[i], b[j], acc[i][j]);
        }
        __syncthreads();
    }

    float bv[8];
    #pragma unroll
    for (int j = 0; j < 8; j++)
        bv[j] = BIAS ? __ldg(&bias[col0 + tx * 8 + j]) : 0.0f;

    #pragma unroll
    for (int i = 0; i < 8; i++) {
        const long r = row0 + ty * 8 + i;
        float4 o0, o1;
        o0.x = acc[i][0] + bv[0]; o0.y = acc[i][1] + bv[1];
        o0.z = acc[i][2] + bv[2]; o0.w = acc[i][3] + bv[3];
        o1.x = acc[i][4] + bv[4]; o1.y = acc[i][5] + bv[5];
        o1.z = acc[i][6] + bv[6]; o1.w = acc[i][7] + bv[7];
        *(float4*)(C + r * N + col0 + tx * 8    ) = o0;
        *(float4*)(C + r * N + col0 + tx * 8 + 4) = o1;
    }
}

// ---------------------------------------------------------------------------
// JAX threefry2x32 (key = (0, 42)), 20 rounds. Verified bit-exact against the
// published test vector (key (0,0), ctr (0,0) -> 0x6B200159, 0x99BA4EFE).
// ---------------------------------------------------------------------------
__device__ __forceinline__ void threefry_0_42(uint32_t x0, uint32_t x1,
                                              uint32_t& o0, uint32_t& o1)
{
    const uint32_t k0 = 0u, k1 = 42u;
    const uint32_t k2 = k0 ^ k1 ^ 0x1BD11BDAu;
    x0 += k0; x1 += k1;
#define TFR(r) { x0 += x1; x1 = (x1 << (r)) | (x1 >> (32 - (r))); x1 ^= x0; }
    TFR(13) TFR(15) TFR(26) TFR(6)
    x0 += k1; x1 += k2 + 1u;
    TFR(17) TFR(29) TFR(16) TFR(24)
    x0 += k2; x1 += k0 + 2u;
    TFR(13) TFR(15) TFR(26) TFR(6)
    x0 += k0; x1 += k1 + 3u;
    TFR(17) TFR(29) TFR(16) TFR(24)
    x0 += k1; x1 += k2 + 4u;
    TFR(13) TFR(15) TFR(26) TFR(6)
    x0 += k2; x1 += k0 + 5u;
#undef TFR
    o0 = x0; o1 = x1;
}

// jax_threefry_partitionable=True (modern JAX default) bit generation:
// element j's counter is its 64-bit linear index -> threefry(key, hi=0, lo=j);
// for 32-bit dtypes bits = out0 ^ out1. Then mantissa-fill uniform in
// [1e-10, 1) (maxval-minval rounds to 1.0f), gumbel = -log(-log(u)).
__device__ __forceinline__ float gumbel_at(uint32_t j)
{
    uint32_t o0, o1;
    threefry_0_42(0u, j, o0, o1);
    const uint32_t bits = o0 ^ o1;
    const float f = __uint_as_float((bits >> 9) | 0x3f800000u) - 1.0f;
    const float u = fmaxf(1e-10f, f + 1e-10f);
    return -logf(-logf(u));
}

__device__ __forceinline__ float gelu_exact(float v)
{
    return 0.5f * v * (1.0f + erff(v * 0.70710678118654752440f));
}

// ---------------------------------------------------------------------------
// Adjacency: one block per (b, s) row; thread t handles entry (s, t).
// corr -> MLP -> logits, + gumbel -> argmax (hard one-hot fwd value),
// force diagonal, row-normalize by integer degree.
// ---------------------------------------------------------------------------
__global__ __launch_bounds__(256)
void adj_kernel(const float* __restrict__ corr,
                const float* __restrict__ W1, const float* __restrict__ b1,
                const float* __restrict__ W2, const float* __restrict__ b2,
                const float* __restrict__ W3, const float* __restrict__ b3,
                float* __restrict__ adj)
{
    const int s = blockIdx.x;
    const int b = blockIdx.y;
    const int t = threadIdx.x;
    const int idx = (b * SS + s) * SS + t;

    const float c = corr[idx];

    float h2[8];
    #pragma unroll
    for (int j = 0; j < 8; j++) h2[j] = __ldg(&b2[j]);
    #pragma unroll
    for (int i = 0; i < 16; i++) {
        const float h = gelu_exact(c * __ldg(&W1[i]) + __ldg(&b1[i]));
        #pragma unroll
        for (int j = 0; j < 8; j++) h2[j] += h * __ldg(&W2[i * 8 + j]);
    }
    float z0 = __ldg(&b3[0]), z1 = __ldg(&b3[1]);
    #pragma unroll
    for (int j = 0; j < 8; j++) {
        const float h = gelu_exact(h2[j]);
        z0 += h * __ldg(&W3[j * 2 + 0]);
        z1 += h * __ldg(&W3[j * 2 + 1]);
    }

    // log_softmax cancels under argmax; ST-estimator forward value = hard one-hot.
    const uint32_t j0 = (uint32_t)idx * 2u;
    const float g0 = gumbel_at(j0);
    const float g1 = gumbel_at(j0 + 1u);
    int sel = (z0 + g0 >= z1 + g1) ? 1 : 0;  // argmax ties -> index 0
    if (t == s) sel = 1;                     // a + (1-a)*I

    const unsigned ball = __ballot_sync(0xffffffffu, sel);
    __shared__ int wdeg[8];
    if ((t & 31) == 0) wdeg[t >> 5] = __popc(ball);
    __syncthreads();
    int deg = 0;
    #pragma unroll
    for (int w = 0; w < 8; w++) deg += wdeg[w];

    adj[idx] = sel ? (1.0f / (float)deg) : 0.0f;  // 1.0 * (1/sum), matches JAX
}

// ---------------------------------------------------------------------------
extern "C" void kernel_launch(void* const* d_in, const int* in_sizes, int n_in,
                              void* d_out, int out_size)
{
    // Default: reference-signature order.
    int iF = 0, iFM = 1, iW1 = 2, ib1 = 3, iW2 = 4, ib2 = 5,
        iW3 = 6, ib3 = 7, iWl = 8, ibl = 9;
    // Guard: alphabetical metadata order (W1,W2,W3,Wl,b1,b2,b3,bl,features,fm)
    if (n_in == 10 && in_sizes[0] == 16 && in_sizes[1] == 128) {
        iW1 = 0; iW2 = 1; iW3 = 2; iWl = 3; ib1 = 4; ib2 = 5; ib3 = 6;
        ibl = 7; iF = 8; iFM = 9;
    }

    const float* features = (const float*)d_in[iF];   // [32,4,256,256]
    const float* fm       = (const float*)d_in[iFM];  // [32,256,256]
    const float* W1       = (const float*)d_in[iW1];
    const float* b1       = (const float*)d_in[ib1];
    const float* W2       = (const float*)d_in[iW2];
    const float* b2       = (const float*)d_in[ib2];
    const float* W3       = (const float*)d_in[iW3];
    const float* b3       = (const float*)d_in[ib3];
    const float* Wl       = (const float*)d_in[iWl];  // [256,256]
    const float* bl       = (const float*)d_in[ibl];  // [256]
    float* out = (float*)d_out;                       // [32,4,256,256]

    float *corr, *adj, *x;
    cudaGetSymbolAddress((void**)&corr, g_corr);
    cudaGetSymbolAddress((void**)&adj,  g_adj);
    cudaGetSymbolAddress((void**)&x,    g_x);

    // 1) corr[b] = fm[b] @ fm[b]^T      (32 x 256^3, NT)
    gemm_kernel<true, false><<<dim3(2, 2, SB), 256>>>(
        fm, fm, nullptr, corr, SS, SS, SS, 1,
        (long)SS * SS, (long)SS * SS, (long)SS * SS);

    // 2) adjacency (MLP + threefry gumbel + degree normalize)
    adj_kernel<<<dim3(SS, SB), 256>>>(corr, W1, b1, W2, b2, W3, b3, adj);

    // 3) x[b,c] = adj[b] @ features[b,c]   (128 x 256^3, NN; A batch = z/4)
    gemm_kernel<false, false><<<dim3(2, 2, SB * SC), 256>>>(
        adj, features, nullptr, x, SS, SS, SS, SC,
        (long)SS * SS, (long)SS * SS, (long)SS * SS);

    // 4) out = x_flat @ Wl + bl            ((32768x256)@(256x256), NN + bias)
    gemm_kernel<false, true><<<dim3(2, 256, 1), 256>>>(
        x, Wl, bl, out, SB * SC * SS, SS, SS, 1, 0, 0, 0);
}

// round 5
// speedup vs baseline: 1.6909x; 1.6909x over previous
#include <cuda_runtime.h>
#include <cstdint>

// Shapes (fixed by the problem): B=32, C=4, S=256, L=Din=Dout=256
#define SB 32
#define SC 4
#define SS 256

// Scratch (static device globals — allowed; no runtime allocation)
__device__ float g_corr[SB * SS * SS];        //  8M floats
__device__ float g_adj [SB * SS * SS];        //  8M floats
__device__ float g_x   [SB * SC * SS * SS];   // 32M floats

// ===========================================================================
// fp32 SGEMM (kept ONLY for step 1: corr = fm @ fm^T, which feeds the argmax
// and therefore must stay bit-identical to the previously-validated path).
// ===========================================================================
template<bool TRANSB, bool BIAS>
__global__ __launch_bounds__(256)
void gemm_kernel(const float* __restrict__ A, const float* __restrict__ B,
                 const float* __restrict__ bias, float* __restrict__ C,
                 int M, int N, int K, int adiv,
                 long strideA, long strideB, long strideC)
{
    const int bz = blockIdx.z;
    A += (long)(bz / adiv) * strideA;
    B += (long)bz * strideB;
    C += (long)bz * strideC;

    __shared__ __align__(16) float As[16][132];
    __shared__ __align__(16) float Bs[16][132];

    const int tid = threadIdx.x;
    const int tx = tid & 15;
    const int ty = tid >> 4;
    const int row0 = blockIdx.y * 128;
    const int col0 = blockIdx.x * 128;

    const int lm  = tid >> 2;
    const int lk4 = (tid & 3) * 4;

    float acc[8][8];
    #pragma unroll
    for (int i = 0; i < 8; i++)
        #pragma unroll
        for (int j = 0; j < 8; j++) acc[i][j] = 0.0f;

    for (int k0 = 0; k0 < K; k0 += 16) {
        {
            float4 v0 = *(const float4*)(A + (long)(row0 + lm     ) * K + k0 + lk4);
            float4 v1 = *(const float4*)(A + (long)(row0 + lm + 64) * K + k0 + lk4);
            As[lk4 + 0][lm] = v0.x; As[lk4 + 1][lm] = v0.y;
            As[lk4 + 2][lm] = v0.z; As[lk4 + 3][lm] = v0.w;
            As[lk4 + 0][lm + 64] = v1.x; As[lk4 + 1][lm + 64] = v1.y;
            As[lk4 + 2][lm + 64] = v1.z; As[lk4 + 3][lm + 64] = v1.w;
        }
        if (TRANSB) {
            float4 v0 = *(const float4*)(B + (long)(col0 + lm     ) * K + k0 + lk4);
            float4 v1 = *(const float4*)(B + (long)(col0 + lm + 64) * K + k0 + lk4);
            Bs[lk4 + 0][lm] = v0.x; Bs[lk4 + 1][lm] = v0.y;
            Bs[lk4 + 2][lm] = v0.z; Bs[lk4 + 3][lm] = v0.w;
            Bs[lk4 + 0][lm + 64] = v1.x; Bs[lk4 + 1][lm + 64] = v1.y;
            Bs[lk4 + 2][lm + 64] = v1.z; Bs[lk4 + 3][lm + 64] = v1.w;
        } else {
            const int bk  = tid >> 5;
            const int bn4 = (tid & 31) * 4;
            float4 v0 = *(const float4*)(B + (long)(k0 + bk    ) * N + col0 + bn4);
            float4 v1 = *(const float4*)(B + (long)(k0 + bk + 8) * N + col0 + bn4);
            *(float4*)(&Bs[bk    ][bn4]) = v0;
            *(float4*)(&Bs[bk + 8][bn4]) = v1;
        }
        __syncthreads();

        #pragma unroll
        for (int kk = 0; kk < 16; kk++) {
            float a[8], b[8];
            *(float4*)&a[0] = *(const float4*)&As[kk][ty * 8];
            *(float4*)&a[4] = *(const float4*)&As[kk][ty * 8 + 4];
            *(float4*)&b[0] = *(const float4*)&Bs[kk][tx * 8];
            *(float4*)&b[4] = *(const float4*)&Bs[kk][tx * 8 + 4];
            #pragma unroll
            for (int i = 0; i < 8; i++)
                #pragma unroll
                for (int j = 0; j < 8; j++)
                    acc[i][j] = fmaf(a[i], b[j], acc[i][j]);
        }
        __syncthreads();
    }

    float bv[8];
    #pragma unroll
    for (int j = 0; j < 8; j++)
        bv[j] = BIAS ? __ldg(&bias[col0 + tx * 8 + j]) : 0.0f;

    #pragma unroll
    for (int i = 0; i < 8; i++) {
        const long r = row0 + ty * 8 + i;
        float4 o0, o1;
        o0.x = acc[i][0] + bv[0]; o0.y = acc[i][1] + bv[1];
        o0.z = acc[i][2] + bv[2]; o0.w = acc[i][3] + bv[3];
        o1.x = acc[i][4] + bv[4]; o1.y = acc[i][5] + bv[5];
        o1.z = acc[i][6] + bv[6]; o1.w = acc[i][7] + bv[7];
        *(float4*)(C + r * N + col0 + tx * 8    ) = o0;
        *(float4*)(C + r * N + col0 + tx * 8 + 4) = o1;
    }
}

// ---- tf32 round-to-nearest convert (plain function; no asm-in-lambda) ----
__device__ __forceinline__ float cvt1_tf32(float v)
{
    uint32_t t;
    asm("cvt.rna.tf32.f32 %0, %1;" : "=r"(t) : "f"(v));
    return __uint_as_float(t);
}
__device__ __forceinline__ float4 cvt_tf32(float4 v)
{
    float4 o;
    o.x = cvt1_tf32(v.x); o.y = cvt1_tf32(v.y);
    o.z = cvt1_tf32(v.z); o.w = cvt1_tf32(v.w);
    return o;
}

// ===========================================================================
// TF32 tensor-core GEMM (steps 3 & 4 only — no discrete decisions downstream).
// C = A @ B (+bias). 128x128 tile, BK=16, 256 threads (8 warps, 2x4 layout,
// warp tile 64x32). mma.sync.m16n8k8 tf32. Double-buffered smem, one
// __syncthreads per K-step. A-frags via ldmatrix.x4 (fp32-as-2xb16 trick).
// ===========================================================================
template<bool BIAS>
__global__ __launch_bounds__(256, 2)
void gemm_tf32(const float* __restrict__ A, const float* __restrict__ B,
               const float* __restrict__ bias, float* __restrict__ C,
               int M, int N, int K, int adiv,
               long strideA, long strideB, long strideC)
{
    const int bz = blockIdx.z;
    A += (long)(bz / adiv) * strideA;
    B += (long)bz * strideB;
    C += (long)bz * strideC;

    __shared__ __align__(16) float As[2][128][20];   // stride 20: LDSM conflict-free
    __shared__ __align__(16) float Bs[2][16][136];   // stride 136: LDS conflict-free

    const int tid  = threadIdx.x;
    const int lane = tid & 31;
    const int warp = tid >> 5;
    const int wm   = warp >> 2;      // 0..1
    const int wn   = warp & 3;       // 0..3
    const int row0 = blockIdx.y * 128;
    const int col0 = blockIdx.x * 128;

    const int arow = tid >> 2;          // 0..63
    const int acol = (tid & 3) * 4;     // 0,4,8,12
    const int brow = tid >> 5;          // 0..7
    const int bcol = (tid & 31) * 4;    // 0..124

    const int lrow  = lane & 15;
    const int lcol4 = (lane >> 4) << 2;

    float acc[4][4][4];
    #pragma unroll
    for (int mf = 0; mf < 4; mf++)
        #pragma unroll
        for (int nf = 0; nf < 4; nf++)
            #pragma unroll
            for (int r = 0; r < 4; r++) acc[mf][nf][r] = 0.0f;

    // prologue: tile 0
    float4 pa0 = *(const float4*)(A + (long)(row0 + arow     ) * K + acol);
    float4 pa1 = *(const float4*)(A + (long)(row0 + arow + 64) * K + acol);
    float4 pb0 = *(const float4*)(B + (long)(brow    ) * N + col0 + bcol);
    float4 pb1 = *(const float4*)(B + (long)(brow + 8) * N + col0 + bcol);
    *(float4*)(&As[0][arow     ][acol]) = cvt_tf32(pa0);
    *(float4*)(&As[0][arow + 64][acol]) = cvt_tf32(pa1);
    *(float4*)(&Bs[0][brow    ][bcol]) = cvt_tf32(pb0);
    *(float4*)(&Bs[0][brow + 8][bcol]) = cvt_tf32(pb1);
    __syncthreads();

    const int nit = K >> 4;
    const int last = nit - 1;
    for (int i = 0; i < nit; i++) {
        const int cur = i & 1;
        if (i < last) {
            const int k0 = (i + 1) << 4;
            pa0 = *(const float4*)(A + (long)(row0 + arow     ) * K + k0 + acol);
            pa1 = *(const float4*)(A + (long)(row0 + arow + 64) * K + k0 + acol);
            pb0 = *(const float4*)(B + (long)(k0 + brow    ) * N + col0 + bcol);
            pb1 = *(const float4*)(B + (long)(k0 + brow + 8) * N + col0 + bcol);
        }

        #pragma unroll
        for (int ks = 0; ks < 2; ks++) {
            const int kc = ks * 8;
            uint32_t a[4][4];
            #pragma unroll
            for (int mf = 0; mf < 4; mf++) {
                const float* p = &As[cur][wm * 64 + mf * 16 + lrow][kc + lcol4];
                uint32_t sa = (uint32_t)__cvta_generic_to_shared(p);
                asm volatile("ldmatrix.sync.aligned.m8n8.x4.shared.b16 {%0,%1,%2,%3}, [%4];"
                             : "=r"(a[mf][0]), "=r"(a[mf][1]), "=r"(a[mf][2]), "=r"(a[mf][3])
                             : "r"(sa));
            }
            uint32_t b[4][2];
            #pragma unroll
            for (int nf = 0; nf < 4; nf++) {
                const int n = wn * 32 + nf * 8 + (lane >> 2);
                b[nf][0] = __float_as_uint(Bs[cur][kc     + (lane & 3)][n]);
                b[nf][1] = __float_as_uint(Bs[cur][kc + 4 + (lane & 3)][n]);
            }
            #pragma unroll
            for (int mf = 0; mf < 4; mf++)
                #pragma unroll
                for (int nf = 0; nf < 4; nf++) {
                    asm volatile(
                        "mma.sync.aligned.m16n8k8.row.col.f32.tf32.tf32.f32 "
                        "{%0,%1,%2,%3}, {%4,%5,%6,%7}, {%8,%9}, {%0,%1,%2,%3};"
                        : "+f"(acc[mf][nf][0]), "+f"(acc[mf][nf][1]),
                          "+f"(acc[mf][nf][2]), "+f"(acc[mf][nf][3])
                        : "r"(a[mf][0]), "r"(a[mf][1]), "r"(a[mf][2]), "r"(a[mf][3]),
                          "r"(b[nf][0]), "r"(b[nf][1]));
                }
        }

        if (i < last) {
            const int nxt = cur ^ 1;
            *(float4*)(&As[nxt][arow     ][acol]) = cvt_tf32(pa0);
            *(float4*)(&As[nxt][arow + 64][acol]) = cvt_tf32(pa1);
            *(float4*)(&Bs[nxt][brow    ][bcol]) = cvt_tf32(pb0);
            *(float4*)(&Bs[nxt][brow + 8][bcol]) = cvt_tf32(pb1);
        }
        __syncthreads();
    }

    // epilogue
    #pragma unroll
    for (int mf = 0; mf < 4; mf++) {
        const long r0 = row0 + wm * 64 + mf * 16 + (lane >> 2);
        const long r1 = r0 + 8;
        #pragma unroll
        for (int nf = 0; nf < 4; nf++) {
            const int c = col0 + wn * 32 + nf * 8 + (lane & 3) * 2;
            float b0 = BIAS ? __ldg(&bias[c])     : 0.0f;
            float b1 = BIAS ? __ldg(&bias[c + 1]) : 0.0f;
            float2 o0 = { acc[mf][nf][0] + b0, acc[mf][nf][1] + b1 };
            float2 o1 = { acc[mf][nf][2] + b0, acc[mf][nf][3] + b1 };
            *(float2*)(C + r0 * N + c) = o0;
            *(float2*)(C + r1 * N + c) = o1;
        }
    }
}

// ---------------------------------------------------------------------------
// JAX threefry2x32 (key = (0, 42)), 20 rounds.
// ---------------------------------------------------------------------------
__device__ __forceinline__ void threefry_0_42(uint32_t x0, uint32_t x1,
                                              uint32_t& o0, uint32_t& o1)
{
    const uint32_t k0 = 0u, k1 = 42u;
    const uint32_t k2 = k0 ^ k1 ^ 0x1BD11BDAu;
    x0 += k0; x1 += k1;
#define TFR(r) { x0 += x1; x1 = (x1 << (r)) | (x1 >> (32 - (r))); x1 ^= x0; }
    TFR(13) TFR(15) TFR(26) TFR(6)
    x0 += k1; x1 += k2 + 1u;
    TFR(17) TFR(29) TFR(16) TFR(24)
    x0 += k2; x1 += k0 + 2u;
    TFR(13) TFR(15) TFR(26) TFR(6)
    x0 += k0; x1 += k1 + 3u;
    TFR(17) TFR(29) TFR(16) TFR(24)
    x0 += k1; x1 += k2 + 4u;
    TFR(13) TFR(15) TFR(26) TFR(6)
    x0 += k2; x1 += k0 + 5u;
#undef TFR
    o0 = x0; o1 = x1;
}

// jax_threefry_partitionable bit generation: counter = 64-bit linear index,
// bits = out0 ^ out1; mantissa-fill uniform in [1e-10, 1); gumbel = -log(-log u)
__device__ __forceinline__ float gumbel_at(uint32_t j)
{
    uint32_t o0, o1;
    threefry_0_42(0u, j, o0, o1);
    const uint32_t bits = o0 ^ o1;
    const float f = __uint_as_float((bits >> 9) | 0x3f800000u) - 1.0f;
    const float u = fmaxf(1e-10f, f + 1e-10f);
    return -logf(-logf(u));
}

__device__ __forceinline__ float gelu_exact(float v)
{
    return 0.5f * v * (1.0f + erff(v * 0.70710678118654752440f));
}

// ---------------------------------------------------------------------------
// Adjacency: one block per (b, s) row; thread t handles entry (s, t).
// ---------------------------------------------------------------------------
__global__ __launch_bounds__(256)
void adj_kernel(const float* __restrict__ corr,
                const float* __restrict__ W1, const float* __restrict__ b1,
                const float* __restrict__ W2, const float* __restrict__ b2,
                const float* __restrict__ W3, const float* __restrict__ b3,
                float* __restrict__ adj)
{
    const int s = blockIdx.x;
    const int b = blockIdx.y;
    const int t = threadIdx.x;
    const int idx = (b * SS + s) * SS + t;

    const float c = corr[idx];

    float h2[8];
    #pragma unroll
    for (int j = 0; j < 8; j++) h2[j] = __ldg(&b2[j]);
    #pragma unroll
    for (int i = 0; i < 16; i++) {
        const float h = gelu_exact(c * __ldg(&W1[i]) + __ldg(&b1[i]));
        #pragma unroll
        for (int j = 0; j < 8; j++) h2[j] += h * __ldg(&W2[i * 8 + j]);
    }
    float z0 = __ldg(&b3[0]), z1 = __ldg(&b3[1]);
    #pragma unroll
    for (int j = 0; j < 8; j++) {
        const float h = gelu_exact(h2[j]);
        z0 += h * __ldg(&W3[j * 2 + 0]);
        z1 += h * __ldg(&W3[j * 2 + 1]);
    }

    const uint32_t j0 = (uint32_t)idx * 2u;
    const float g0 = gumbel_at(j0);
    const float g1 = gumbel_at(j0 + 1u);
    int sel = (z0 + g0 >= z1 + g1) ? 1 : 0;
    if (t == s) sel = 1;

    const unsigned ball = __ballot_sync(0xffffffffu, sel);
    __shared__ int wdeg[8];
    if ((t & 31) == 0) wdeg[t >> 5] = __popc(ball);
    __syncthreads();
    int deg = 0;
    #pragma unroll
    for (int w = 0; w < 8; w++) deg += wdeg[w];

    adj[idx] = sel ? (1.0f / (float)deg) : 0.0f;
}

// ---------------------------------------------------------------------------
extern "C" void kernel_launch(void* const* d_in, const int* in_sizes, int n_in,
                              void* d_out, int out_size)
{
    int iF = 0, iFM = 1, iW1 = 2, ib1 = 3, iW2 = 4, ib2 = 5,
        iW3 = 6, ib3 = 7, iWl = 8, ibl = 9;
    if (n_in == 10 && in_sizes[0] == 16 && in_sizes[1] == 128) {
        iW1 = 0; iW2 = 1; iW3 = 2; iWl = 3; ib1 = 4; ib2 = 5; ib3 = 6;
        ibl = 7; iF = 8; iFM = 9;
    }

    const float* features = (const float*)d_in[iF];   // [32,4,256,256]
    const float* fm       = (const float*)d_in[iFM];  // [32,256,256]
    const float* W1       = (const float*)d_in[iW1];
    const float* b1       = (const float*)d_in[ib1];
    const float* W2       = (const float*)d_in[iW2];
    const float* b2       = (const float*)d_in[ib2];
    const float* W3       = (const float*)d_in[iW3];
    const float* b3       = (const float*)d_in[ib3];
    const float* Wl       = (const float*)d_in[iWl];  // [256,256]
    const float* bl       = (const float*)d_in[ibl];  // [256]
    float* out = (float*)d_out;                       // [32,4,256,256]

    float *corr, *adj, *x;
    cudaGetSymbolAddress((void**)&corr, g_corr);
    cudaGetSymbolAddress((void**)&adj,  g_adj);
    cudaGetSymbolAddress((void**)&x,    g_x);

    // 1) corr[b] = fm[b] @ fm[b]^T   (fp32 — feeds argmax, must stay exact)
    gemm_kernel<true, false><<<dim3(2, 2, SB), 256>>>(
        fm, fm, nullptr, corr, SS, SS, SS, 1,
        (long)SS * SS, (long)SS * SS, (long)SS * SS);

    // 2) adjacency (MLP + threefry gumbel + degree normalize) — exact
    adj_kernel<<<dim3(SS, SB), 256>>>(corr, W1, b1, W2, b2, W3, b3, adj);

    // 3) x[b,c] = adj[b] @ features[b,c]   (TF32 tensor cores)
    gemm_tf32<false><<<dim3(2, 2, SB * SC), 256>>>(
        adj, features, nullptr, x, SS, SS, SS, SC,
        (long)SS * SS, (long)SS * SS, (long)SS * SS);

    // 4) out = x_flat @ Wl + bl            (TF32 tensor cores)
    gemm_tf32<true><<<dim3(2, 256, 1), 256>>>(
        x, Wl, bl, out, SB * SC * SS, SS, SS, 1, 0, 0, 0);
}

// round 7
// speedup vs baseline: 1.8486x; 1.0933x over previous
#include <cuda_runtime.h>
#include <cstdint>

// Shapes (fixed by the problem): B=32, C=4, S=256, L=Din=Dout=256
#define SB 32
#define SC 4
#define SS 256

// Scratch (static device globals — allowed; no runtime allocation)
__device__ float g_corr[SB * SS * SS];        //  8M floats
__device__ float g_adj [SB * SS * SS];        //  8M floats
__device__ float g_x   [SB * SC * SS * SS];   // 32M floats

// ===========================================================================
// fp32 SGEMM (kept ONLY for step 1: corr = fm @ fm^T, which feeds the argmax
// and therefore must stay bit-identical to the validated path).
// ===========================================================================
template<bool TRANSB, bool BIAS>
__global__ __launch_bounds__(256)
void gemm_kernel(const float* __restrict__ A, const float* __restrict__ B,
                 const float* __restrict__ bias, float* __restrict__ C,
                 int M, int N, int K, int adiv,
                 long strideA, long strideB, long strideC)
{
    const int bz = blockIdx.z;
    A += (long)(bz / adiv) * strideA;
    B += (long)bz * strideB;
    C += (long)bz * strideC;

    __shared__ __align__(16) float As[16][132];
    __shared__ __align__(16) float Bs[16][132];

    const int tid = threadIdx.x;
    const int tx = tid & 15;
    const int ty = tid >> 4;
    const int row0 = blockIdx.y * 128;
    const int col0 = blockIdx.x * 128;

    const int lm  = tid >> 2;
    const int lk4 = (tid & 3) * 4;

    float acc[8][8];
    #pragma unroll
    for (int i = 0; i < 8; i++)
        #pragma unroll
        for (int j = 0; j < 8; j++) acc[i][j] = 0.0f;

    for (int k0 = 0; k0 < K; k0 += 16) {
        {
            float4 v0 = *(const float4*)(A + (long)(row0 + lm     ) * K + k0 + lk4);
            float4 v1 = *(const float4*)(A + (long)(row0 + lm + 64) * K + k0 + lk4);
            As[lk4 + 0][lm] = v0.x; As[lk4 + 1][lm] = v0.y;
            As[lk4 + 2][lm] = v0.z; As[lk4 + 3][lm] = v0.w;
            As[lk4 + 0][lm + 64] = v1.x; As[lk4 + 1][lm + 64] = v1.y;
            As[lk4 + 2][lm + 64] = v1.z; As[lk4 + 3][lm + 64] = v1.w;
        }
        if (TRANSB) {
            float4 v0 = *(const float4*)(B + (long)(col0 + lm     ) * K + k0 + lk4);
            float4 v1 = *(const float4*)(B + (long)(col0 + lm + 64) * K + k0 + lk4);
            Bs[lk4 + 0][lm] = v0.x; Bs[lk4 + 1][lm] = v0.y;
            Bs[lk4 + 2][lm] = v0.z; Bs[lk4 + 3][lm] = v0.w;
            Bs[lk4 + 0][lm + 64] = v1.x; Bs[lk4 + 1][lm + 64] = v1.y;
            Bs[lk4 + 2][lm + 64] = v1.z; Bs[lk4 + 3][lm + 64] = v1.w;
        } else {
            const int bk  = tid >> 5;
            const int bn4 = (tid & 31) * 4;
            float4 v0 = *(const float4*)(B + (long)(k0 + bk    ) * N + col0 + bn4);
            float4 v1 = *(const float4*)(B + (long)(k0 + bk + 8) * N + col0 + bn4);
            *(float4*)(&Bs[bk    ][bn4]) = v0;
            *(float4*)(&Bs[bk + 8][bn4]) = v1;
        }
        __syncthreads();

        #pragma unroll
        for (int kk = 0; kk < 16; kk++) {
            float a[8], b[8];
            *(float4*)&a[0] = *(const float4*)&As[kk][ty * 8];
            *(float4*)&a[4] = *(const float4*)&As[kk][ty * 8 + 4];
            *(float4*)&b[0] = *(const float4*)&Bs[kk][tx * 8];
            *(float4*)&b[4] = *(const float4*)&Bs[kk][tx * 8 + 4];
            #pragma unroll
            for (int i = 0; i < 8; i++)
                #pragma unroll
                for (int j = 0; j < 8; j++)
                    acc[i][j] = fmaf(a[i], b[j], acc[i][j]);
        }
        __syncthreads();
    }

    float bv[8];
    #pragma unroll
    for (int j = 0; j < 8; j++)
        bv[j] = BIAS ? __ldg(&bias[col0 + tx * 8 + j]) : 0.0f;

    #pragma unroll
    for (int i = 0; i < 8; i++) {
        const long r = row0 + ty * 8 + i;
        float4 o0, o1;
        o0.x = acc[i][0] + bv[0]; o0.y = acc[i][1] + bv[1];
        o0.z = acc[i][2] + bv[2]; o0.w = acc[i][3] + bv[3];
        o1.x = acc[i][4] + bv[4]; o1.y = acc[i][5] + bv[5];
        o1.z = acc[i][6] + bv[6]; o1.w = acc[i][7] + bv[7];
        *(float4*)(C + r * N + col0 + tx * 8    ) = o0;
        *(float4*)(C + r * N + col0 + tx * 8 + 4) = o1;
    }
}

// ---- tf32 round-to-nearest convert (plain function; no asm-in-lambda) ----
__device__ __forceinline__ float cvt1_tf32(float v)
{
    uint32_t t;
    asm("cvt.rna.tf32.f32 %0, %1;" : "=r"(t) : "f"(v));
    return __uint_as_float(t);
}
__device__ __forceinline__ float4 cvt_tf32(float4 v)
{
    float4 o;
    o.x = cvt1_tf32(v.x); o.y = cvt1_tf32(v.y);
    o.z = cvt1_tf32(v.z); o.w = cvt1_tf32(v.w);
    return o;
}

// ===========================================================================
// TF32 tensor-core GEMM (steps 3 & 4 — unchanged from R5's passing kernel).
// ===========================================================================
template<bool BIAS>
__global__ __launch_bounds__(256, 2)
void gemm_tf32(const float* __restrict__ A, const float* __restrict__ B,
               const float* __restrict__ bias, float* __restrict__ C,
               int M, int N, int K, int adiv,
               long strideA, long strideB, long strideC)
{
    const int bz = blockIdx.z;
    A += (long)(bz / adiv) * strideA;
    B += (long)bz * strideB;
    C += (long)bz * strideC;

    __shared__ __align__(16) float As[2][128][20];   // stride 20: LDSM conflict-free
    __shared__ __align__(16) float Bs[2][16][136];   // stride 136: LDS conflict-free

    const int tid  = threadIdx.x;
    const int lane = tid & 31;
    const int warp = tid >> 5;
    const int wm   = warp >> 2;      // 0..1
    const int wn   = warp & 3;       // 0..3
    const int row0 = blockIdx.y * 128;
    const int col0 = blockIdx.x * 128;

    const int arow = tid >> 2;          // 0..63
    const int acol = (tid & 3) * 4;     // 0,4,8,12
    const int brow = tid >> 5;          // 0..7
    const int bcol = (tid & 31) * 4;    // 0..124

    const int lrow  = lane & 15;
    const int lcol4 = (lane >> 4) << 2;

    float acc[4][4][4];
    #pragma unroll
    for (int mf = 0; mf < 4; mf++)
        #pragma unroll
        for (int nf = 0; nf < 4; nf++)
            #pragma unroll
            for (int r = 0; r < 4; r++) acc[mf][nf][r] = 0.0f;

    // prologue: tile 0
    float4 pa0 = *(const float4*)(A + (long)(row0 + arow     ) * K + acol);
    float4 pa1 = *(const float4*)(A + (long)(row0 + arow + 64) * K + acol);
    float4 pb0 = *(const float4*)(B + (long)(brow    ) * N + col0 + bcol);
    float4 pb1 = *(const float4*)(B + (long)(brow + 8) * N + col0 + bcol);
    *(float4*)(&As[0][arow     ][acol]) = cvt_tf32(pa0);
    *(float4*)(&As[0][arow + 64][acol]) = cvt_tf32(pa1);
    *(float4*)(&Bs[0][brow    ][bcol]) = cvt_tf32(pb0);
    *(float4*)(&Bs[0][brow + 8][bcol]) = cvt_tf32(pb1);
    __syncthreads();

    const int nit = K >> 4;
    const int last = nit - 1;
    for (int i = 0; i < nit; i++) {
        const int cur = i & 1;
        if (i < last) {
            const int k0 = (i + 1) << 4;
            pa0 = *(const float4*)(A + (long)(row0 + arow     ) * K + k0 + acol);
            pa1 = *(const float4*)(A + (long)(row0 + arow + 64) * K + k0 + acol);
            pb0 = *(const float4*)(B + (long)(k0 + brow    ) * N + col0 + bcol);
            pb1 = *(const float4*)(B + (long)(k0 + brow + 8) * N + col0 + bcol);
        }

        #pragma unroll
        for (int ks = 0; ks < 2; ks++) {
            const int kc = ks * 8;
            uint32_t a[4][4];
            #pragma unroll
            for (int mf = 0; mf < 4; mf++) {
                const float* p = &As[cur][wm * 64 + mf * 16 + lrow][kc + lcol4];
                uint32_t sa = (uint32_t)__cvta_generic_to_shared(p);
                asm volatile("ldmatrix.sync.aligned.m8n8.x4.shared.b16 {%0,%1,%2,%3}, [%4];"
                             : "=r"(a[mf][0]), "=r"(a[mf][1]), "=r"(a[mf][2]), "=r"(a[mf][3])
                             : "r"(sa));
            }
            uint32_t b[4][2];
            #pragma unroll
            for (int nf = 0; nf < 4; nf++) {
                const int n = wn * 32 + nf * 8 + (lane >> 2);
                b[nf][0] = __float_as_uint(Bs[cur][kc     + (lane & 3)][n]);
                b[nf][1] = __float_as_uint(Bs[cur][kc + 4 + (lane & 3)][n]);
            }
            #pragma unroll
            for (int mf = 0; mf < 4; mf++)
                #pragma unroll
                for (int nf = 0; nf < 4; nf++) {
                    asm volatile(
                        "mma.sync.aligned.m16n8k8.row.col.f32.tf32.tf32.f32 "
                        "{%0,%1,%2,%3}, {%4,%5,%6,%7}, {%8,%9}, {%0,%1,%2,%3};"
                        : "+f"(acc[mf][nf][0]), "+f"(acc[mf][nf][1]),
                          "+f"(acc[mf][nf][2]), "+f"(acc[mf][nf][3])
                        : "r"(a[mf][0]), "r"(a[mf][1]), "r"(a[mf][2]), "r"(a[mf][3]),
                          "r"(b[nf][0]), "r"(b[nf][1]));
                }
        }

        if (i < last) {
            const int nxt = cur ^ 1;
            *(float4*)(&As[nxt][arow     ][acol]) = cvt_tf32(pa0);
            *(float4*)(&As[nxt][arow + 64][acol]) = cvt_tf32(pa1);
            *(float4*)(&Bs[nxt][brow    ][bcol]) = cvt_tf32(pb0);
            *(float4*)(&Bs[nxt][brow + 8][bcol]) = cvt_tf32(pb1);
        }
        __syncthreads();
    }

    // epilogue
    #pragma unroll
    for (int mf = 0; mf < 4; mf++) {
        const long r0 = row0 + wm * 64 + mf * 16 + (lane >> 2);
        const long r1 = r0 + 8;
        #pragma unroll
        for (int nf = 0; nf < 4; nf++) {
            const int c = col0 + wn * 32 + nf * 8 + (lane & 3) * 2;
            float b0 = BIAS ? __ldg(&bias[c])     : 0.0f;
            float b1 = BIAS ? __ldg(&bias[c + 1]) : 0.0f;
            float2 o0 = { acc[mf][nf][0] + b0, acc[mf][nf][1] + b1 };
            float2 o1 = { acc[mf][nf][2] + b0, acc[mf][nf][3] + b1 };
            *(float2*)(C + r0 * N + c) = o0;
            *(float2*)(C + r1 * N + c) = o1;
        }
    }
}

// ---------------------------------------------------------------------------
// JAX threefry2x32 (key = (0, 42)), 20 rounds.
// ---------------------------------------------------------------------------
__device__ __forceinline__ void threefry_0_42(uint32_t x0, uint32_t x1,
                                              uint32_t& o0, uint32_t& o1)
{
    const uint32_t k0 = 0u, k1 = 42u;
    const uint32_t k2 = k0 ^ k1 ^ 0x1BD11BDAu;
    x0 += k0; x1 += k1;
#define TFR(r) { x0 += x1; x1 = (x1 << (r)) | (x1 >> (32 - (r))); x1 ^= x0; }
    TFR(13) TFR(15) TFR(26) TFR(6)
    x0 += k1; x1 += k2 + 1u;
    TFR(17) TFR(29) TFR(16) TFR(24)
    x0 += k2; x1 += k0 + 2u;
    TFR(13) TFR(15) TFR(26) TFR(6)
    x0 += k0; x1 += k1 + 3u;
    TFR(17) TFR(29) TFR(16) TFR(24)
    x0 += k1; x1 += k2 + 4u;
    TFR(13) TFR(15) TFR(26) TFR(6)
    x0 += k2; x1 += k0 + 5u;
#undef TFR
    o0 = x0; o1 = x1;
}

// jax_threefry_partitionable bit generation: counter = 64-bit linear index,
// bits = out0 ^ out1; mantissa-fill uniform in [1e-10, 1); gumbel = -log(-log u)
__device__ __forceinline__ float gumbel_at(uint32_t j)
{
    uint32_t o0, o1;
    threefry_0_42(0u, j, o0, o1);
    const uint32_t bits = o0 ^ o1;
    const float f = __uint_as_float((bits >> 9) | 0x3f800000u) - 1.0f;
    const float u = fmaxf(1e-10f, f + 1e-10f);
    return -logf(-logf(u));
}

__device__ __forceinline__ float gelu_exact(float v)
{
    return 0.5f * v * (1.0f + erff(v * 0.70710678118654752440f));
}

// ---------------------------------------------------------------------------
// Adjacency v2: one block = 4 rows; each thread = 4 consecutive elements.
// Weights staged in smem once (amortized 4x); per-element arithmetic is the
// bit-identical sequence of v1 (same op order, same erff/logf/threefry).
// ---------------------------------------------------------------------------
__global__ __launch_bounds__(256)
void adj_kernel(const float* __restrict__ corr,
                const float* __restrict__ W1, const float* __restrict__ b1,
                const float* __restrict__ W2, const float* __restrict__ b2,
                const float* __restrict__ W3, const float* __restrict__ b3,
                float* __restrict__ adj)
{
    __shared__ float sW1[16], sb1[16], sW2[128], sb2[8], sW3[16], sb3[2];
    __shared__ int wsum[8];

    const int tid = threadIdx.x;
    if (tid < 16)        sW1[tid]       = W1[tid];
    else if (tid < 32)   sb1[tid - 16]  = b1[tid - 16];
    else if (tid < 160)  sW2[tid - 32]  = W2[tid - 32];
    else if (tid < 168)  sb2[tid - 160] = b2[tid - 160];
    else if (tid < 184)  sW3[tid - 168] = W3[tid - 168];
    else if (tid < 186)  sb3[tid - 184] = b3[tid - 184];
    __syncthreads();

    const int er = tid >> 6;                    // local row 0..3
    const int r  = blockIdx.x * 4 + er;         // global row (b*256+s)
    const int s  = r & 255;
    const int c0 = (tid & 63) * 4;              // column base
    const long idx = (long)r * 256 + c0;

    const float4 cv = *(const float4*)(corr + idx);
    float c[4] = {cv.x, cv.y, cv.z, cv.w};

    // MLP layer 1+2 for 4 elements, weights read once per (i,j)
    float h2[4][8];
    #pragma unroll
    for (int j = 0; j < 8; j++) {
        const float bj = sb2[j];
        #pragma unroll
        for (int e = 0; e < 4; e++) h2[e][j] = bj;
    }
    #pragma unroll
    for (int i = 0; i < 16; i++) {
        const float w1 = sW1[i], bb = sb1[i];
        float h[4];
        #pragma unroll
        for (int e = 0; e < 4; e++) h[e] = gelu_exact(c[e] * w1 + bb);
        #pragma unroll
        for (int j = 0; j < 8; j++) {
            const float w2 = sW2[i * 8 + j];
            #pragma unroll
            for (int e = 0; e < 4; e++) h2[e][j] += h[e] * w2;
        }
    }
    // layer 3
    float z0[4], z1[4];
    {
        const float bz0 = sb3[0], bz1 = sb3[1];
        #pragma unroll
        for (int e = 0; e < 4; e++) { z0[e] = bz0; z1[e] = bz1; }
    }
    #pragma unroll
    for (int j = 0; j < 8; j++) {
        const float w30 = sW3[j * 2 + 0], w31 = sW3[j * 2 + 1];
        #pragma unroll
        for (int e = 0; e < 4; e++) {
            const float hh = gelu_exact(h2[e][j]);
            z0[e] += hh * w30;
            z1[e] += hh * w31;
        }
    }

    // Gumbel argmax (hard one-hot forward value) + forced diagonal
    int mask = 0;
    #pragma unroll
    for (int e = 0; e < 4; e++) {
        const uint32_t j0 = (uint32_t)(idx + e) * 2u;
        const float g0 = gumbel_at(j0);
        const float g1 = gumbel_at(j0 + 1u);
        int sel = (z0[e] + g0 >= z1[e] + g1) ? 1 : 0;
        if (c0 + e == s) sel = 1;
        mask |= sel << e;
    }

    // integer degree per row (threads er*64..er*64+63 = warps 2er, 2er+1)
    const unsigned tot = __reduce_add_sync(0xffffffffu, (unsigned)__popc(mask));
    if ((tid & 31) == 0) wsum[tid >> 5] = (int)tot;
    __syncthreads();
    const int deg = wsum[er * 2] + wsum[er * 2 + 1];
    const float inv = 1.0f / (float)deg;

    float4 o;
    o.x = (mask & 1) ? inv : 0.0f;
    o.y = (mask & 2) ? inv : 0.0f;
    o.z = (mask & 4) ? inv : 0.0f;
    o.w = (mask & 8) ? inv : 0.0f;
    *(float4*)(adj + idx) = o;
}

// ---------------------------------------------------------------------------
extern "C" void kernel_launch(void* const* d_in, const int* in_sizes, int n_in,
                              void* d_out, int out_size)
{
    int iF = 0, iFM = 1, iW1 = 2, ib1 = 3, iW2 = 4, ib2 = 5,
        iW3 = 6, ib3 = 7, iWl = 8, ibl = 9;
    if (n_in == 10 && in_sizes[0] == 16 && in_sizes[1] == 128) {
        iW1 = 0; iW2 = 1; iW3 = 2; iWl = 3; ib1 = 4; ib2 = 5; ib3 = 6;
        ibl = 7; iF = 8; iFM = 9;
    }

    const float* features = (const float*)d_in[iF];   // [32,4,256,256]
    const float* fm       = (const float*)d_in[iFM];  // [32,256,256]
    const float* W1       = (const float*)d_in[iW1];
    const float* b1       = (const float*)d_in[ib1];
    const float* W2       = (const float*)d_in[iW2];
    const float* b2       = (const float*)d_in[ib2];
    const float* W3       = (const float*)d_in[iW3];
    const float* b3       = (const float*)d_in[ib3];
    const float* Wl       = (const float*)d_in[iWl];  // [256,256]
    const float* bl       = (const float*)d_in[ibl];  // [256]
    float* out = (float*)d_out;                       // [32,4,256,256]

    float *corr, *adj, *x;
    cudaGetSymbolAddress((void**)&corr, g_corr);
    cudaGetSymbolAddress((void**)&adj,  g_adj);
    cudaGetSymbolAddress((void**)&x,    g_x);

    // 1) corr[b] = fm[b] @ fm[b]^T   (fp32 — feeds argmax, must stay exact)
    gemm_kernel<true, false><<<dim3(2, 2, SB), 256>>>(
        fm, fm, nullptr, corr, SS, SS, SS, 1,
        (long)SS * SS, (long)SS * SS, (long)SS * SS);

    // 2) adjacency (MLP + threefry gumbel + degree normalize) — bit-exact
    adj_kernel<<<(SB * SS) / 4, 256>>>(corr, W1, b1, W2, b2, W3, b3, adj);

    // 3) x[b,c] = adj[b] @ features[b,c]   (TF32 tensor cores)
    gemm_tf32<false><<<dim3(2, 2, SB * SC), 256>>>(
        adj, features, nullptr, x, SS, SS, SS, SC,
        (long)SS * SS, (long)SS * SS, (long)SS * SS);

    // 4) out = x_flat @ Wl + bl            (TF32 tensor cores)
    gemm_tf32<true><<<dim3(2, 256, 1), 256>>>(
        x, Wl, bl, out, SB * SC * SS, SS, SS, 1, 0, 0, 0);
}